// round 11
// baseline (speedup 1.0000x reference)
#include <cuda_runtime.h>
#include <math.h>

typedef unsigned long long u64;

// ---------------------------------------------------------------------------
// Problem constants
// ---------------------------------------------------------------------------
#define BATCH 128
#define C0 3
#define H0 224
#define OH0 55
#define FH0 220
#define NPIX0 (FH0*FH0)      // 48400
#define NBLK0 (OH0*OH0)      // 3025
#define PH 110
#define NPIXP (PH*PH)        // 12100
#define OH1 53
#define FH1 159
#define NPIX1 (FH1*FH1)      // 25281
#define NBLK1 (OH1*OH1)      // 2809
#define NOUT 1000
#define KTOT NPIX1           // 25281
// fc gemm
#define SPLITS 37
#define KCHUNK 688           // 43*16;  37*688 = 25456 >= 25281
#define WPITCH 17            // W smem pitch (conflict-free LDS.32)
// conv0 weight smem pitch: 20 words -> 80B rows, 16B-aligned LDS.128
#define C0PITCH 20

// ---------------------------------------------------------------------------
// Device scratch
// ---------------------------------------------------------------------------
__device__ float g_xT[C0 * H0 * H0 * BATCH];        // [c][h][w][b]
__device__ float g_z0[NPIX0 * BATCH];               // [pix][b]
__device__ float g_p[NPIXP * BATCH];                // [pix][b]
__device__ float g_z1[NPIX1 * BATCH];               // [k][b]
__device__ float g_p0s[NBLK0 * BATCH];              // conv0 per-location LN partials
__device__ float g_p0q[NBLK0 * BATCH];
__device__ float g_p1s[NBLK1 * BATCH];              // conv1 per-location LN partials
__device__ float g_p1q[NBLK1 * BATCH];
__device__ float g_stats[4 * BATCH];                // m0,r0 | m1,r1
__device__ float g_gpart[SPLITS * 1024 * BATCH];    // [s][o][b]
__device__ float g_logT[NOUT * BATCH];              // [o][b]

// ---------------------------------------------------------------------------
// helpers
// ---------------------------------------------------------------------------
__device__ __forceinline__ void fma2(u64 &acc, u64 a, u64 w) {
    asm("fma.rn.f32x2 %0, %1, %2, %0;" : "+l"(acc) : "l"(a), "l"(w));
}
__device__ __forceinline__ u64 dup2(float w) {
    u64 r;
    asm("mov.b64 %0, {%1, %1};" : "=l"(r) : "f"(w));
    return r;
}

// ---------------------------------------------------------------------------
// 1) Transpose x[B][3][224][224] -> xT[c][h][w][B]
// ---------------------------------------------------------------------------
__global__ void k_transpose(const float* __restrict__ x) {
    int c = blockIdx.x / H0;
    int h = blockIdx.x % H0;
    __shared__ float tile[32][225];
    for (int b0 = 0; b0 < BATCH; b0 += 32) {
        for (int i = threadIdx.x; i < 32 * H0; i += 256) {
            int bb = i / H0, w = i % H0;
            tile[bb][w] = x[(((size_t)(b0 + bb) * C0 + c) * H0 + h) * H0 + w];
        }
        __syncthreads();
        for (int i = threadIdx.x; i < 32 * H0; i += 256) {
            int w = i >> 5, bb = i & 31;
            g_xT[((size_t)(c * H0 + h) * H0 + w) * BATCH + b0 + bb] = tile[bb][w];
        }
        __syncthreads();
    }
}

// ---------------------------------------------------------------------------
// 2) conv0: block = 1 location, THREAD = 1 batch computing all 16 oc.
//    x: one coalesced LDG.32 per warp-tap -> x read exactly once (297 MB).
//    w: smem [t][C0PITCH] floats, broadcast LDS.128 as (oc,oc+1) pairs.
//    acc = 8 u64 = 16 regs; LN partials thread-local.
// ---------------------------------------------------------------------------
__global__ __launch_bounds__(128) void k_conv0(const float* __restrict__ w0,
                                               const float* __restrict__ b0) {
    __shared__ __align__(16) float ws[192 * C0PITCH];
    int loc = blockIdx.x;
    int oh = loc / OH0, ow = loc % OH0;
    int b = threadIdx.x;
    const float* wloc = w0 + (size_t)loc * 3072;
    for (int i = b; i < 3072; i += 128) {
        int oc = i / 192, t = i % 192;
        ws[t * C0PITCH + oc] = wloc[i];
    }
    __syncthreads();

    u64 acc[8];
#pragma unroll
    for (int p = 0; p < 8; p++) acc[p] = 0ull;

    int ih0 = oh * 4, iw0 = ow * 4;
#pragma unroll 1
    for (int c = 0; c < 3; c++) {
#pragma unroll 1
        for (int kh = 0; kh < 8; kh++) {
            const float* xr = g_xT + ((size_t)((c * H0 + ih0 + kh) * H0) + iw0) * BATCH + b;
            const float* wr = ws + (c * 8 + kh) * 8 * C0PITCH;
#pragma unroll
            for (int kw = 0; kw < 8; kw++) {
                u64 xd = dup2(xr[kw * BATCH]);
                const ulonglong2* wp = (const ulonglong2*)(wr + kw * C0PITCH);
                ulonglong2 wa = wp[0], wb2 = wp[1], wc2 = wp[2], wd2 = wp[3];
                fma2(acc[0], xd, wa.x);  fma2(acc[1], xd, wa.y);
                fma2(acc[2], xd, wb2.x); fma2(acc[3], xd, wb2.y);
                fma2(acc[4], xd, wc2.x); fma2(acc[5], xd, wc2.y);
                fma2(acc[6], xd, wd2.x); fma2(acc[7], xd, wd2.y);
            }
        }
    }

    // epilogue: bias + relu + store + thread-local LN partials
    float s = 0.f, q = 0.f;
#pragma unroll
    for (int p = 0; p < 8; p++) {
        int oc0 = 2 * p, oc1 = 2 * p + 1;
        float2 v = *reinterpret_cast<float2*>(&acc[p]);
        float r0 = fmaxf(v.x + b0[oc0 * NBLK0 + loc], 0.f);
        float r1 = fmaxf(v.y + b0[oc1 * NBLK0 + loc], 0.f);
        s += r0 + r1; q += r0 * r0 + r1 * r1;
        int row0 = oh * 4 + (oc0 >> 2), col0 = ow * 4 + (oc0 & 3);
        int row1 = oh * 4 + (oc1 >> 2), col1 = ow * 4 + (oc1 & 3);
        g_z0[(size_t)(row0 * FH0 + col0) * BATCH + b] = r0;
        g_z0[(size_t)(row1 * FH0 + col1) * BATCH + b] = r1;
    }
    g_p0s[(size_t)loc * BATCH + b] = s;
    g_p0q[(size_t)loc * BATCH + b] = q;
}

// ---------------------------------------------------------------------------
// 3) LN final: per-location partials -> mean/rstd
// ---------------------------------------------------------------------------
__global__ void k_ln_final(int which, int nblk, float inv_n, int stat_ofs) {
    const float* __restrict__ ps = which ? g_p1s : g_p0s;
    const float* __restrict__ pq = which ? g_p1q : g_p0q;
    int b = blockIdx.x;       // 128 blocks
    int t = threadIdx.x;      // 256 threads
    float s = 0.f, q = 0.f;
    for (int i = t; i < nblk; i += 256) {
        s += ps[(size_t)i * BATCH + b];
        q += pq[(size_t)i * BATCH + b];
    }
    __shared__ float rs[256], rq[256];
    rs[t] = s; rq[t] = q;
    __syncthreads();
    for (int st = 128; st > 0; st >>= 1) {
        if (t < st) { rs[t] += rs[t + st]; rq[t] += rq[t + st]; }
        __syncthreads();
    }
    if (t == 0) {
        float m = rs[0] * inv_n;
        float v = rq[0] * inv_n - m * m;
        g_stats[stat_ofs + b] = m;
        g_stats[stat_ofs + BATCH + b] = rsqrtf(v + 1e-5f);
    }
}

// ---------------------------------------------------------------------------
// 4) LN-apply + 2x2 maxpool
// ---------------------------------------------------------------------------
__global__ void k_pool(const float* __restrict__ g0, const float* __restrict__ be0) {
    int pix = blockIdx.x;
    int oi = pix / PH, oj = pix % PH;
    int b = threadIdx.x;
    float m = g_stats[b], r = g_stats[BATCH + b];
    float best = -INFINITY;
#pragma unroll
    for (int a = 0; a < 2; a++)
#pragma unroll
        for (int c = 0; c < 2; c++) {
            int sp = (2 * oi + a) * FH0 + (2 * oj + c);
            float v = g_z0[(size_t)sp * BATCH + b];
            float nv = (v - m) * r * g0[sp] + be0[sp];
            best = fmaxf(best, nv);
        }
    g_p[(size_t)pix * BATCH + b] = best;
}

// ---------------------------------------------------------------------------
// 5) conv1 + bias + relu + LN-partials -> z1 [k][b]
// ---------------------------------------------------------------------------
__global__ __launch_bounds__(128) void k_conv1(const float* __restrict__ w1,
                                               const float* __restrict__ b1) {
    __shared__ __align__(16) float wsT[36 * 12];
    int ow = blockIdx.x, oh = blockIdx.y, tid = threadIdx.x;
    const float* wloc = w1 + (size_t)(oh * OH1 + ow) * 324;
    if (tid < 108) {
        for (int i = tid; i < 324; i += 108) {
            int oc = i / 36, t = i % 36;
            wsT[t * 12 + oc] = wloc[i];
        }
    }
    __syncthreads();
    float acc[9];
#pragma unroll
    for (int u = 0; u < 9; u++) acc[u] = 0.f;
    int ih0 = 2 * oh, iw0 = 2 * ow;
#pragma unroll 1
    for (int kh = 0; kh < 6; kh++) {
#pragma unroll
        for (int kw = 0; kw < 6; kw++) {
            int t = kh * 6 + kw;
            float xv = g_p[(size_t)((ih0 + kh) * PH + iw0 + kw) * BATCH + tid];
            float4 wA = *(const float4*)&wsT[t * 12];
            float4 wB = *(const float4*)&wsT[t * 12 + 4];
            float w8 = wsT[t * 12 + 8];
            acc[0] += xv * wA.x; acc[1] += xv * wA.y; acc[2] += xv * wA.z; acc[3] += xv * wA.w;
            acc[4] += xv * wB.x; acc[5] += xv * wB.y; acc[6] += xv * wB.z; acc[7] += xv * wB.w;
            acc[8] += xv * w8;
        }
    }
    float s = 0.f, q = 0.f;
#pragma unroll
    for (int oc = 0; oc < 9; oc++) {
        float r = fmaxf(acc[oc] + b1[oc * (OH1 * OH1) + oh * OH1 + ow], 0.f);
        s += r; q += r * r;
        int row = 3 * oh + oc / 3, col = 3 * ow + oc % 3;
        g_z1[(size_t)(row * FH1 + col) * BATCH + tid] = r;
    }
    int blk = oh * OH1 + ow;
    g_p1s[(size_t)blk * BATCH + tid] = s;
    g_p1q[(size_t)blk * BATCH + tid] = q;
}

// ---------------------------------------------------------------------------
// 6) FC GEMM — R8's exact known-good version (355 us baseline).
//    Broadcast-A; W gmem row-pair LDG; W smem [row][WPITCH] un-duplicated;
//    in-register dup via mov.b64; no prefetch (register cap (256,2)).
// ---------------------------------------------------------------------------
__global__ __launch_bounds__(256, 2) void k_gemm(const float* __restrict__ fcw,
                                                 const float* __restrict__ g1,
                                                 const float* __restrict__ be1) {
    __shared__ __align__(16) float As[16 * 128];          // [kk][b]
    __shared__ __align__(16) float Ws[128 * WPITCH];      // [row][kk] padded
    __shared__ float sm_m[BATCH], sm_r[BATCH];
    int tid = threadIdx.x;
    if (tid < BATCH) {
        sm_m[tid] = g_stats[256 + tid];
        sm_r[tid] = g_stats[384 + tid];
    }
    int obase = blockIdx.x * 128;
    int k0 = blockIdx.y * KCHUNK;
    int kend = min(k0 + KCHUNK, KTOT);
    int oy = tid & 31, py = tid >> 5;
    int wid = tid >> 5, lane = tid & 31;
    int lrow = lane >> 4, lk = lane & 15;   // W loader: row-in-pair, k index

    u64 acc[4][8];                      // [o-group j][b-pair i]
#pragma unroll
    for (int j = 0; j < 4; j++)
#pragma unroll
        for (int i = 0; i < 8; i++) acc[j][i] = 0ull;

    __syncthreads();

    for (int kt = k0; kt < kend; kt += 16) {
        // --- A tile: z1[kt..kt+15][0..127] with LN fused ---
        {
            int k = kt + (tid >> 4);
            int bb = (tid & 15) * 8;
            float v[8]; float gk = 0.f, bk = 0.f;
            if (k < kend) {
                const float* src = g_z1 + (size_t)k * BATCH + bb;
                float4 v0 = *(const float4*)src;
                float4 v1 = *(const float4*)(src + 4);
                v[0] = v0.x; v[1] = v0.y; v[2] = v0.z; v[3] = v0.w;
                v[4] = v1.x; v[5] = v1.y; v[6] = v1.z; v[7] = v1.w;
                gk = g1[k]; bk = be1[k];
            } else {
#pragma unroll
                for (int j = 0; j < 8; j++) v[j] = 0.f;
            }
            float o[8];
#pragma unroll
            for (int j = 0; j < 8; j++)
                o[j] = (v[j] - sm_m[bb + j]) * sm_r[bb + j] * gk + bk;
            float4* dst = (float4*)&As[(tid >> 4) * 128 + bb];
            dst[0] = make_float4(o[0], o[1], o[2], o[3]);
            dst[1] = make_float4(o[4], o[5], o[6], o[7]);
        }
        // --- W tile: warp covers a row-pair per iteration ---
        {
            int kg = kt + lk;
            bool kok = (kg < kend);
#pragma unroll
            for (int r = 0; r < 8; r++) {
                int p = r * 8 + wid;               // row-pair index 0..63
                int row = 2 * p + lrow;            // 0..127
                int og = obase + row;
                float v = (og < NOUT && kok) ? fcw[(size_t)og * KTOT + kg] : 0.f;
                Ws[row * WPITCH + lk] = v;
            }
        }
        __syncthreads();
#pragma unroll 4
        for (int kk = 0; kk < 16; kk++) {
            const float* ab = &As[kk * 128 + py * 16];
            ulonglong2 a01 = *(const ulonglong2*)(ab);       // broadcast
            ulonglong2 a23 = *(const ulonglong2*)(ab + 4);
            ulonglong2 a45 = *(const ulonglong2*)(ab + 8);
            ulonglong2 a67 = *(const ulonglong2*)(ab + 12);
            u64 a[8] = {a01.x, a01.y, a23.x, a23.y, a45.x, a45.y, a67.x, a67.y};
            u64 w0 = dup2(Ws[(oy      ) * WPITCH + kk]);
            u64 w1 = dup2(Ws[(oy +  32) * WPITCH + kk]);
            u64 w2 = dup2(Ws[(oy +  64) * WPITCH + kk]);
            u64 w3 = dup2(Ws[(oy +  96) * WPITCH + kk]);
#pragma unroll
            for (int i = 0; i < 8; i++) {
                fma2(acc[0][i], a[i], w0);
                fma2(acc[1][i], a[i], w1);
                fma2(acc[2][i], a[i], w2);
                fma2(acc[3][i], a[i], w3);
            }
        }
        __syncthreads();
    }
    // epilogue: partials -> g_gpart[s][o(1024)][b]
#pragma unroll
    for (int j = 0; j < 4; j++) {
        int og = obase + oy + 32 * j;
        float* dst = g_gpart + ((size_t)blockIdx.y * 1024 + og) * BATCH + py * 16;
        ulonglong2* d2 = (ulonglong2*)dst;
        d2[0] = make_ulonglong2(acc[j][0], acc[j][1]);
        d2[1] = make_ulonglong2(acc[j][2], acc[j][3]);
        d2[2] = make_ulonglong2(acc[j][4], acc[j][5]);
        d2[3] = make_ulonglong2(acc[j][6], acc[j][7]);
    }
}

// ---------------------------------------------------------------------------
// 7) Split-K reduce (+fcb) -> logits [o][b]
// ---------------------------------------------------------------------------
__global__ void k_redsum(const float* __restrict__ fcb) {
    int o = blockIdx.x;
    int b = threadIdx.x;
    float s = fcb[o];
#pragma unroll
    for (int sp = 0; sp < SPLITS; sp++)
        s += g_gpart[((size_t)sp * 1024 + o) * BATCH + b];
    g_logT[o * BATCH + b] = s;
}

// ---------------------------------------------------------------------------
// 8) Softmax per batch row -> out[b][1000]
// ---------------------------------------------------------------------------
__global__ void k_softmax(float* __restrict__ out) {
    int b = blockIdx.x;
    int tid = threadIdx.x;  // 256
    __shared__ float red[256];
    float vals[4];
    float mx = -INFINITY;
#pragma unroll
    for (int j = 0; j < 4; j++) {
        int o = tid + j * 256;
        vals[j] = (o < NOUT) ? g_logT[o * BATCH + b] : -INFINITY;
        mx = fmaxf(mx, vals[j]);
    }
    red[tid] = mx;
    __syncthreads();
    for (int s = 128; s > 0; s >>= 1) {
        if (tid < s) red[tid] = fmaxf(red[tid], red[tid + s]);
        __syncthreads();
    }
    float gmx = red[0];
    __syncthreads();
    float se = 0.f;
#pragma unroll
    for (int j = 0; j < 4; j++) {
        int o = tid + j * 256;
        if (o < NOUT) { vals[j] = expf(vals[j] - gmx); se += vals[j]; }
    }
    red[tid] = se;
    __syncthreads();
    for (int s = 128; s > 0; s >>= 1) {
        if (tid < s) red[tid] += red[tid + s];
        __syncthreads();
    }
    float inv = 1.f / red[0];
#pragma unroll
    for (int j = 0; j < 4; j++) {
        int o = tid + j * 256;
        if (o < NOUT) out[(size_t)b * NOUT + o] = vals[j] * inv;
    }
}

// ---------------------------------------------------------------------------
// launch
// ---------------------------------------------------------------------------
extern "C" void kernel_launch(void* const* d_in, const int* in_sizes, int n_in,
                              void* d_out, int out_size) {
    const float* x   = (const float*)d_in[0];
    const float* w0  = (const float*)d_in[1];
    const float* b0  = (const float*)d_in[2];
    const float* g0  = (const float*)d_in[3];
    const float* be0 = (const float*)d_in[4];
    const float* w1  = (const float*)d_in[5];
    const float* b1  = (const float*)d_in[6];
    const float* g1  = (const float*)d_in[7];
    const float* be1 = (const float*)d_in[8];
    const float* fcw = (const float*)d_in[9];
    const float* fcb = (const float*)d_in[10];
    float* out = (float*)d_out;

    k_transpose<<<C0 * H0, 256>>>(x);
    k_conv0<<<NBLK0, 128>>>(w0, b0);
    k_ln_final<<<128, 256>>>(0, NBLK0, 1.f / NPIX0, 0);
    k_pool<<<NPIXP, 128>>>(g0, be0);
    k_conv1<<<dim3(OH1, OH1), 128>>>(w1, b1);
    k_ln_final<<<128, 256>>>(1, NBLK1, 1.f / NPIX1, 256);
    k_gemm<<<dim3(8, SPLITS), 256>>>(fcw, g1, be1);
    k_redsum<<<NOUT, 128>>>(fcb);
    k_softmax<<<BATCH, 256>>>(out);
}

// round 14
// speedup vs baseline: 1.6070x; 1.6070x over previous
#include <cuda_runtime.h>
#include <math.h>
#include <stdint.h>

typedef unsigned long long u64;

// ---------------------------------------------------------------------------
// Problem constants
// ---------------------------------------------------------------------------
#define BATCH 128
#define C0 3
#define H0 224
#define OH0 55
#define FH0 220
#define NPIX0 (FH0*FH0)      // 48400
#define NBLK0 (OH0*OH0)      // 3025
#define PH 110
#define NPIXP (PH*PH)        // 12100
#define OH1 53
#define FH1 159
#define NPIX1 (FH1*FH1)      // 25281
#define NBLK1 (OH1*OH1)      // 2809
#define NOUT 1000
#define KTOT NPIX1           // 25281
// fc gemm
#define SPLITS 37
#define KCHUNK 688           // 43*16;  37*688 = 25456 >= 25281
#define WPITCH 17            // W smem pitch (conflict-free LDS.32)

// ---------------------------------------------------------------------------
// Device scratch
// ---------------------------------------------------------------------------
__device__ float g_xT[C0 * H0 * H0 * BATCH];        // [c][h][w][b]
__device__ float g_z0[NPIX0 * BATCH];               // [pix][b]
__device__ float g_p[NPIXP * BATCH];                // [pix][b]
__device__ float g_z1[NPIX1 * BATCH];               // [k][b]
__device__ float g_p0s[NBLK0 * BATCH];              // conv0 per-block LN partials
__device__ float g_p0q[NBLK0 * BATCH];
__device__ float g_p1s[NBLK1 * BATCH];              // conv1 per-block LN partials
__device__ float g_p1q[NBLK1 * BATCH];
__device__ float g_stats[4 * BATCH];                // m0,r0 | m1,r1
__device__ float g_gpart[SPLITS * 1024 * BATCH];    // [s][o][b]
__device__ float g_logT[NOUT * BATCH];              // [o][b]

// ---------------------------------------------------------------------------
// helpers
// ---------------------------------------------------------------------------
__device__ __forceinline__ void fma2(u64 &acc, u64 a, u64 w) {
    asm("fma.rn.f32x2 %0, %1, %2, %0;" : "+l"(acc) : "l"(a), "l"(w));
}
__device__ __forceinline__ u64 dup2(float w) {
    u64 r;
    asm("mov.b64 %0, {%1, %1};" : "=l"(r) : "f"(w));
    return r;
}
__device__ __forceinline__ uint32_t smem_u32(const void* p) {
    uint32_t a;
    asm("{ .reg .u64 t; cvta.to.shared.u64 t, %1; cvt.u32.u64 %0, t; }" : "=r"(a) : "l"(p));
    return a;
}

// ---------------------------------------------------------------------------
// 1) Transpose x[B][3][224][224] -> xT[c][h][w][B]
// ---------------------------------------------------------------------------
__global__ void k_transpose(const float* __restrict__ x) {
    int c = blockIdx.x / H0;
    int h = blockIdx.x % H0;
    __shared__ float tile[32][225];
    for (int b0 = 0; b0 < BATCH; b0 += 32) {
        for (int i = threadIdx.x; i < 32 * H0; i += 256) {
            int bb = i / H0, w = i % H0;
            tile[bb][w] = x[(((size_t)(b0 + bb) * C0 + c) * H0 + h) * H0 + w];
        }
        __syncthreads();
        for (int i = threadIdx.x; i < 32 * H0; i += 256) {
            int w = i >> 5, bb = i & 31;
            g_xT[((size_t)(c * H0 + h) * H0 + w) * BATCH + b0 + bb] = tile[bb][w];
        }
        __syncthreads();
    }
}

// ---------------------------------------------------------------------------
// 2) conv0 + bias + relu + LN-partials (R8 version: warp = oc-group,
//    weights broadcast from smem dup-pairs; x redundancy absorbed by L1)
// ---------------------------------------------------------------------------
__global__ __launch_bounds__(128) void k_conv0(const float* __restrict__ w0,
                                               const float* __restrict__ b0) {
    __shared__ __align__(16) float ws2[192 * 18 * 2];  // (t*18+oc) dup pairs
    __shared__ __align__(16) float redS[4][128], redQ[4][128];
    int ow = blockIdx.x, oh = blockIdx.y, tid = threadIdx.x;
    const float* wloc = w0 + (size_t)(oh * OH0 + ow) * 3072;
    for (int i = tid; i < 3072; i += 128) {
        float w = wloc[i];
        int oc = i / 192, t = i % 192;
        *(float2*)&ws2[(t * 18 + oc) * 2] = make_float2(w, w);
    }
    __syncthreads();

    int og = tid >> 5, bq = tid & 31;   // warp = oc-group, thread = 4 batches
    u64 acc[4][2];
#pragma unroll
    for (int u = 0; u < 4; u++) { acc[u][0] = 0ull; acc[u][1] = 0ull; }

    int ih0 = oh * 4, iw0 = ow * 4;
#pragma unroll 1
    for (int c = 0; c < 3; c++) {
#pragma unroll 1
        for (int kh = 0; kh < 8; kh++) {
            const float* xr = g_xT + ((size_t)((c * H0 + ih0 + kh) * H0) + iw0) * BATCH + 4 * bq;
            const float* wr = &ws2[((c * 8 + kh) * 8 * 18 + og * 4) * 2];
#pragma unroll
            for (int kw = 0; kw < 8; kw++) {
                ulonglong2 xv = *(const ulonglong2*)(xr + kw * BATCH);
                const ulonglong2* wp = (const ulonglong2*)(wr + kw * 36);
                ulonglong2 w01 = wp[0], w23 = wp[1];   // broadcast LDS
                fma2(acc[0][0], xv.x, w01.x); fma2(acc[0][1], xv.y, w01.x);
                fma2(acc[1][0], xv.x, w01.y); fma2(acc[1][1], xv.y, w01.y);
                fma2(acc[2][0], xv.x, w23.x); fma2(acc[2][1], xv.y, w23.x);
                fma2(acc[3][0], xv.x, w23.y); fma2(acc[3][1], xv.y, w23.y);
            }
        }
    }
    float s0=0.f,s1=0.f,s2=0.f,s3=0.f, q0=0.f,q1=0.f,q2=0.f,q3=0.f;
#pragma unroll
    for (int u = 0; u < 4; u++) {
        int oc = og * 4 + u;
        float bias = b0[oc * (OH0 * OH0) + oh * OH0 + ow];
        float2 r0 = *reinterpret_cast<float2*>(&acc[u][0]);
        float2 r1 = *reinterpret_cast<float2*>(&acc[u][1]);
        float4 r = make_float4(fmaxf(r0.x + bias, 0.f), fmaxf(r0.y + bias, 0.f),
                               fmaxf(r1.x + bias, 0.f), fmaxf(r1.y + bias, 0.f));
        s0 += r.x; q0 += r.x * r.x;
        s1 += r.y; q1 += r.y * r.y;
        s2 += r.z; q2 += r.z * r.z;
        s3 += r.w; q3 += r.w * r.w;
        int row = oh * 4 + (oc >> 2), col = ow * 4 + (oc & 3);
        *(float4*)&g_z0[(size_t)(row * FH0 + col) * BATCH + 4 * bq] = r;
    }
    *(float4*)&redS[og][4 * bq] = make_float4(s0, s1, s2, s3);
    *(float4*)&redQ[og][4 * bq] = make_float4(q0, q1, q2, q3);
    __syncthreads();
    if (og == 0) {
        int blk = oh * OH0 + ow;
        float4 S = *(float4*)&redS[0][4 * bq];
        float4 Q = *(float4*)&redQ[0][4 * bq];
#pragma unroll
        for (int w = 1; w < 4; w++) {
            float4 a = *(float4*)&redS[w][4 * bq];
            float4 b = *(float4*)&redQ[w][4 * bq];
            S.x += a.x; S.y += a.y; S.z += a.z; S.w += a.w;
            Q.x += b.x; Q.y += b.y; Q.z += b.z; Q.w += b.w;
        }
        *(float4*)&g_p0s[(size_t)blk * BATCH + 4 * bq] = S;
        *(float4*)&g_p0q[(size_t)blk * BATCH + 4 * bq] = Q;
    }
}

// ---------------------------------------------------------------------------
// 3) LN final: per-block partials -> mean/rstd
// ---------------------------------------------------------------------------
__global__ void k_ln_final(int which, int nblk, float inv_n, int stat_ofs) {
    const float* __restrict__ ps = which ? g_p1s : g_p0s;
    const float* __restrict__ pq = which ? g_p1q : g_p0q;
    int b = blockIdx.x;       // 128 blocks
    int t = threadIdx.x;      // 256 threads
    float s = 0.f, q = 0.f;
    for (int i = t; i < nblk; i += 256) {
        s += ps[(size_t)i * BATCH + b];
        q += pq[(size_t)i * BATCH + b];
    }
    __shared__ float rs[256], rq[256];
    rs[t] = s; rq[t] = q;
    __syncthreads();
    for (int st = 128; st > 0; st >>= 1) {
        if (t < st) { rs[t] += rs[t + st]; rq[t] += rq[t + st]; }
        __syncthreads();
    }
    if (t == 0) {
        float m = rs[0] * inv_n;
        float v = rq[0] * inv_n - m * m;
        g_stats[stat_ofs + b] = m;
        g_stats[stat_ofs + BATCH + b] = rsqrtf(v + 1e-5f);
    }
}

// ---------------------------------------------------------------------------
// 4) LN-apply + 2x2 maxpool
// ---------------------------------------------------------------------------
__global__ void k_pool(const float* __restrict__ g0, const float* __restrict__ be0) {
    int pix = blockIdx.x;
    int oi = pix / PH, oj = pix % PH;
    int b = threadIdx.x;
    float m = g_stats[b], r = g_stats[BATCH + b];
    float best = -INFINITY;
#pragma unroll
    for (int a = 0; a < 2; a++)
#pragma unroll
        for (int c = 0; c < 2; c++) {
            int sp = (2 * oi + a) * FH0 + (2 * oj + c);
            float v = g_z0[(size_t)sp * BATCH + b];
            float nv = (v - m) * r * g0[sp] + be0[sp];
            best = fmaxf(best, nv);
        }
    g_p[(size_t)pix * BATCH + b] = best;
}

// ---------------------------------------------------------------------------
// 5) conv1 + bias + relu + LN-partials -> z1 [k][b]
// ---------------------------------------------------------------------------
__global__ __launch_bounds__(128) void k_conv1(const float* __restrict__ w1,
                                               const float* __restrict__ b1) {
    __shared__ __align__(16) float wsT[36 * 12];
    int ow = blockIdx.x, oh = blockIdx.y, tid = threadIdx.x;
    const float* wloc = w1 + (size_t)(oh * OH1 + ow) * 324;
    if (tid < 108) {
        for (int i = tid; i < 324; i += 108) {
            int oc = i / 36, t = i % 36;
            wsT[t * 12 + oc] = wloc[i];
        }
    }
    __syncthreads();
    float acc[9];
#pragma unroll
    for (int u = 0; u < 9; u++) acc[u] = 0.f;
    int ih0 = 2 * oh, iw0 = 2 * ow;
#pragma unroll 1
    for (int kh = 0; kh < 6; kh++) {
#pragma unroll
        for (int kw = 0; kw < 6; kw++) {
            int t = kh * 6 + kw;
            float xv = g_p[(size_t)((ih0 + kh) * PH + iw0 + kw) * BATCH + tid];
            float4 wA = *(const float4*)&wsT[t * 12];
            float4 wB = *(const float4*)&wsT[t * 12 + 4];
            float w8 = wsT[t * 12 + 8];
            acc[0] += xv * wA.x; acc[1] += xv * wA.y; acc[2] += xv * wA.z; acc[3] += xv * wA.w;
            acc[4] += xv * wB.x; acc[5] += xv * wB.y; acc[6] += xv * wB.z; acc[7] += xv * wB.w;
            acc[8] += xv * w8;
        }
    }
    float s = 0.f, q = 0.f;
#pragma unroll
    for (int oc = 0; oc < 9; oc++) {
        float r = fmaxf(acc[oc] + b1[oc * (OH1 * OH1) + oh * OH1 + ow], 0.f);
        s += r; q += r * r;
        int row = 3 * oh + oc / 3, col = 3 * ow + oc % 3;
        g_z1[(size_t)(row * FH1 + col) * BATCH + tid] = r;
    }
    int blk = oh * OH1 + ow;
    g_p1s[(size_t)blk * BATCH + tid] = s;
    g_p1q[(size_t)blk * BATCH + tid] = q;
}

// ---------------------------------------------------------------------------
// 6) FC GEMM — R8 structure + cp.async W pipeline.
//    W: triple-buffered smem, cp.async (no register cost, zfill predication).
//    A: double-buffered. ONE __syncthreads per tile; max 1-iter thread skew
//    means every writer target differs from any laggard-reader buffer.
// ---------------------------------------------------------------------------
__global__ __launch_bounds__(256, 2) void k_gemm(const float* __restrict__ fcw,
                                                 const float* __restrict__ g1,
                                                 const float* __restrict__ be1) {
    __shared__ __align__(16) float As[2][16 * 128];       // [buf][kk][b]
    __shared__ __align__(16) float Ws[3][128 * WPITCH];   // [buf][row][kk]
    __shared__ float sm_m[BATCH], sm_r[BATCH];
    int tid = threadIdx.x;
    if (tid < BATCH) {
        sm_m[tid] = g_stats[256 + tid];
        sm_r[tid] = g_stats[384 + tid];
    }
    int obase = blockIdx.x * 128;
    int k0 = blockIdx.y * KCHUNK;
    int kend = min(k0 + KCHUNK, KTOT);
    int oy = tid & 31, py = tid >> 5;
    int wid = tid >> 5, lane = tid & 31;
    int lrow = lane >> 4, lk = lane & 15;   // W loader: row-in-pair, k index

    u64 acc[4][8];                      // [o-group j][b-pair i]
#pragma unroll
    for (int j = 0; j < 4; j++)
#pragma unroll
        for (int i = 0; i < 8; i++) acc[j][i] = 0ull;

    uint32_t wsAddr0 = smem_u32(&Ws[0][0]);
    // issue this thread's 8 cp.asyncs for W tile at kt into stage s
    auto cpW = [&](int kt, int s) {
        int kg = kt + lk;
        uint32_t sb = wsAddr0 + (uint32_t)(s * 128 * WPITCH * 4);
        bool kok = (kg < kend);
#pragma unroll
        for (int r = 0; r < 8; r++) {
            int row = 2 * (r * 8 + wid) + lrow;
            int og = obase + row;
            bool ok = (og < NOUT) && kok;
            const float* src = fcw + (ok ? ((size_t)og * KTOT + kg) : 0);
            uint32_t srcsz = ok ? 4u : 0u;
            asm volatile("cp.async.ca.shared.global [%0], [%1], 4, %2;"
                :: "r"(sb + (uint32_t)((row * WPITCH + lk) * 4)), "l"(src), "r"(srcsz)
                : "memory");
        }
    };

    __syncthreads();   // sm_m/sm_r visible
    int nt = (kend - k0 + 15) >> 4;
    cpW(k0, 0);
    asm volatile("cp.async.commit_group;" ::: "memory");

    for (int t = 0; t < nt; t++) {
        int bA = t & 1, bW = t % 3;
        int kt = k0 + 16 * t;
        // --- A tile: z1 load + LN + STS into As[bA] ---
        {
            int k = kt + (tid >> 4);
            int bb = (tid & 15) * 8;
            float v[8]; float gk = 0.f, bk = 0.f;
            if (k < kend) {
                const float* src = g_z1 + (size_t)k * BATCH + bb;
                float4 v0 = *(const float4*)src;
                float4 v1 = *(const float4*)(src + 4);
                v[0] = v0.x; v[1] = v0.y; v[2] = v0.z; v[3] = v0.w;
                v[4] = v1.x; v[5] = v1.y; v[6] = v1.z; v[7] = v1.w;
                gk = g1[k]; bk = be1[k];
            } else {
#pragma unroll
                for (int j = 0; j < 8; j++) v[j] = 0.f;
            }
            float o[8];
#pragma unroll
            for (int j = 0; j < 8; j++)
                o[j] = (v[j] - sm_m[bb + j]) * sm_r[bb + j] * gk + bk;
            float4* dst = (float4*)&As[bA][(tid >> 4) * 128 + bb];
            dst[0] = make_float4(o[0], o[1], o[2], o[3]);
            dst[1] = make_float4(o[4], o[5], o[6], o[7]);
        }
        // --- prefetch next W tile ---
        if (t + 1 < nt) cpW(kt + 16, (t + 1) % 3);
        asm volatile("cp.async.commit_group;" ::: "memory");
        asm volatile("cp.async.wait_group 1;" ::: "memory");  // tile t's W done
        __syncthreads();
        // --- compute ---
#pragma unroll 4
        for (int kk = 0; kk < 16; kk++) {
            const float* ab = &As[bA][kk * 128 + py * 16];
            ulonglong2 a01 = *(const ulonglong2*)(ab);       // broadcast
            ulonglong2 a23 = *(const ulonglong2*)(ab + 4);
            ulonglong2 a45 = *(const ulonglong2*)(ab + 8);
            ulonglong2 a67 = *(const ulonglong2*)(ab + 12);
            u64 a[8] = {a01.x, a01.y, a23.x, a23.y, a45.x, a45.y, a67.x, a67.y};
            u64 w0 = dup2(Ws[bW][(oy      ) * WPITCH + kk]);
            u64 w1 = dup2(Ws[bW][(oy +  32) * WPITCH + kk]);
            u64 w2 = dup2(Ws[bW][(oy +  64) * WPITCH + kk]);
            u64 w3 = dup2(Ws[bW][(oy +  96) * WPITCH + kk]);
#pragma unroll
            for (int i = 0; i < 8; i++) {
                fma2(acc[0][i], a[i], w0);
                fma2(acc[1][i], a[i], w1);
                fma2(acc[2][i], a[i], w2);
                fma2(acc[3][i], a[i], w3);
            }
        }
    }
    // epilogue: partials -> g_gpart[s][o(1024)][b]
#pragma unroll
    for (int j = 0; j < 4; j++) {
        int og = obase + oy + 32 * j;
        float* dst = g_gpart + ((size_t)blockIdx.y * 1024 + og) * BATCH + py * 16;
        ulonglong2* d2 = (ulonglong2*)dst;
        d2[0] = make_ulonglong2(acc[j][0], acc[j][1]);
        d2[1] = make_ulonglong2(acc[j][2], acc[j][3]);
        d2[2] = make_ulonglong2(acc[j][4], acc[j][5]);
        d2[3] = make_ulonglong2(acc[j][6], acc[j][7]);
    }
}

// ---------------------------------------------------------------------------
// 7) Split-K reduce (+fcb) -> logits [o][b]
// ---------------------------------------------------------------------------
__global__ void k_redsum(const float* __restrict__ fcb) {
    int o = blockIdx.x;
    int b = threadIdx.x;
    float s = fcb[o];
#pragma unroll
    for (int sp = 0; sp < SPLITS; sp++)
        s += g_gpart[((size_t)sp * 1024 + o) * BATCH + b];
    g_logT[o * BATCH + b] = s;
}

// ---------------------------------------------------------------------------
// 8) Softmax per batch row -> out[b][1000]
// ---------------------------------------------------------------------------
__global__ void k_softmax(float* __restrict__ out) {
    int b = blockIdx.x;
    int tid = threadIdx.x;  // 256
    __shared__ float red[256];
    float vals[4];
    float mx = -INFINITY;
#pragma unroll
    for (int j = 0; j < 4; j++) {
        int o = tid + j * 256;
        vals[j] = (o < NOUT) ? g_logT[o * BATCH + b] : -INFINITY;
        mx = fmaxf(mx, vals[j]);
    }
    red[tid] = mx;
    __syncthreads();
    for (int s = 128; s > 0; s >>= 1) {
        if (tid < s) red[tid] = fmaxf(red[tid], red[tid + s]);
        __syncthreads();
    }
    float gmx = red[0];
    __syncthreads();
    float se = 0.f;
#pragma unroll
    for (int j = 0; j < 4; j++) {
        int o = tid + j * 256;
        if (o < NOUT) { vals[j] = expf(vals[j] - gmx); se += vals[j]; }
    }
    red[tid] = se;
    __syncthreads();
    for (int s = 128; s > 0; s >>= 1) {
        if (tid < s) red[tid] += red[tid + s];
        __syncthreads();
    }
    float inv = 1.f / red[0];
#pragma unroll
    for (int j = 0; j < 4; j++) {
        int o = tid + j * 256;
        if (o < NOUT) out[(size_t)b * NOUT + o] = vals[j] * inv;
    }
}

// ---------------------------------------------------------------------------
// launch
// ---------------------------------------------------------------------------
extern "C" void kernel_launch(void* const* d_in, const int* in_sizes, int n_in,
                              void* d_out, int out_size) {
    const float* x   = (const float*)d_in[0];
    const float* w0  = (const float*)d_in[1];
    const float* b0  = (const float*)d_in[2];
    const float* g0  = (const float*)d_in[3];
    const float* be0 = (const float*)d_in[4];
    const float* w1  = (const float*)d_in[5];
    const float* b1  = (const float*)d_in[6];
    const float* g1  = (const float*)d_in[7];
    const float* be1 = (const float*)d_in[8];
    const float* fcw = (const float*)d_in[9];
    const float* fcb = (const float*)d_in[10];
    float* out = (float*)d_out;

    k_transpose<<<C0 * H0, 256>>>(x);
    k_conv0<<<dim3(OH0, OH0), 128>>>(w0, b0);
    k_ln_final<<<128, 256>>>(0, NBLK0, 1.f / NPIX0, 0);
    k_pool<<<NPIXP, 128>>>(g0, be0);
    k_conv1<<<dim3(OH1, OH1), 128>>>(w1, b1);
    k_ln_final<<<128, 256>>>(1, NBLK1, 1.f / NPIX1, 256);
    k_gemm<<<dim3(8, SPLITS), 256>>>(fcw, g1, be1);
    k_redsum<<<NOUT, 128>>>(fcb);
    k_softmax<<<BATCH, 256>>>(out);
}